// round 9
// baseline (speedup 1.0000x reference)
#include <cuda_runtime.h>
#include <cuda_bf16.h>
#include <cstdint>
#include <math.h>

// Problem constants
#define PLANE   (2048*2048)       // 4,194,304 pixels per channel plane
#define NBINS   4913              // 17^3 distinct compact keys (289a+17b+c)
#define NFEAT   20

#define K1_BLOCKS  148
#define K1_THREADS 1024
#define K2_THREADS 256
#define K2_WARPS   (K2_THREADS / 32)
#define K2_BLOCKS  ((NBINS + K2_THREADS - 1) / K2_THREADS)   // 20

#define MODE_INT8   0
#define MODE_INT32  1
#define MODE_FP32   2
#define MODE_BF16   3

// ---------------------------------------------------------------------------
// Global scratch. CUDA zeroes __device__ globals at module load. Invariant
// across launches / graph replays: g_hist, g_accum, g_ticket are ZERO on
// entry — kernel 2 re-zeroes everything it consumes. g_stage is fully
// overwritten every launch (from constant inputs -> deterministic).
// ---------------------------------------------------------------------------
__device__ unsigned int g_hist[2 * NBINS];   // [msb bins | lsb bins]
__device__ int          g_accum[NFEAT];
__device__ unsigned int g_ticket;
// Compact, int32-normalized LUT rows: bin j -> 10 int4 = {msb[20] | lsb[20]}
__device__ int4         g_stage[NBINS * 10]; // 786 KB

// Scalar fetch for non-int32 upcast modes (fallback path only).
__device__ __forceinline__ int fetch_lut(const void* __restrict__ tab, int mode, long long e)
{
    switch (mode) {
        case MODE_FP32:  return (int)((const float*)tab)[e];
        case MODE_BF16:  return (int)__bfloat162float(((const __nv_bfloat16*)tab)[e]);
        default:         return (int)((const signed char*)tab)[e];
    }
}

// ---------------------------------------------------------------------------
// Kernel 1: joint histogram + LUT staging.
// ATOMS-bound (~15us) with ~2TB/s spare DRAM headroom — the dtype sniff and
// the 2.4MB staging copy hide under it. Staging writes the touched LUT rows
// (stride 1280B scatter) into a contiguous interleaved int32 array so that
// kernel 2 is branch-free and perfectly coalesced.
// ---------------------------------------------------------------------------
__global__ void __launch_bounds__(K1_THREADS, 1)
hist_kernel(const float* __restrict__ x_in, const float* __restrict__ x_s,
            const void* __restrict__ msb, const void* __restrict__ lsb)
{
    __shared__ unsigned int hm[NBINS];
    __shared__ unsigned int hl[NBINS];
    __shared__ int s_mode;

    const int tid = threadIdx.x;

    // --- dtype sniff: warp 0 of EVERY block (batched loads; L2-shared) ---
    if (tid < 32) {
        const int* w = (const int*)msb;
        int v[8];
        #pragma unroll
        for (int s = 0; s < 8; s++) v[s] = w[tid + 32 * s];

        bool small = true, flt = true, bfl = true;
        #pragma unroll
        for (int s = 0; s < 8; s++) {
            int x = v[s];
            if (x < -32 || x > 31) small = false;
            float f = __int_as_float(x);
            if (!(isfinite(f) && f == truncf(f) && fabsf(f) <= 32.f)) flt = false;
            unsigned u = (unsigned)x;
            float h0 = __bfloat162float(__ushort_as_bfloat16((unsigned short)(u & 0xFFFFu)));
            float h1 = __bfloat162float(__ushort_as_bfloat16((unsigned short)(u >> 16)));
            if (!(isfinite(h0) && h0 == truncf(h0) && fabsf(h0) <= 32.f &&
                  isfinite(h1) && h1 == truncf(h1) && fabsf(h1) <= 32.f)) bfl = false;
        }
        int m;
        if      (__all_sync(0xffffffffu, small)) m = MODE_INT32;
        else if (__all_sync(0xffffffffu, flt))   m = MODE_FP32;
        else if (__all_sync(0xffffffffu, bfl))   m = MODE_BF16;
        else                                     m = MODE_INT8;
        if (tid == 0) s_mode = m;
    }
    for (int k = tid; k < NBINS; k += K1_THREADS) { hm[k] = 0u; hl[k] = 0u; }
    __syncthreads();

    // --- LUT staging: grid-stride over 4913 bins x 5 chunks per table ---
    {
        const int mode = s_mode;
        const int gstr = K1_BLOCKS * K1_THREADS;
        if (mode == MODE_INT32) {
            const int4* m4 = (const int4*)msb;
            const int4* l4 = (const int4*)lsb;
            for (int t = blockIdx.x * K1_THREADS + tid; t < NBINS * 5; t += gstr) {
                const int j = t / 5, q = t - 5 * j;
                // row j: ints [320j, 320j+20) = int4 [80j, 80j+5)
                g_stage[j * 10 + q]     = m4[80L * j + q];
                g_stage[j * 10 + 5 + q] = l4[80L * j + q];
            }
        } else {
            for (int t = blockIdx.x * K1_THREADS + tid; t < NBINS * 5; t += gstr) {
                const int j = t / 5, q = t - 5 * j;
                const long long base = 320LL * j + 4LL * q;
                int4 vm, vl;
                vm.x = fetch_lut(msb, mode, base + 0); vm.y = fetch_lut(msb, mode, base + 1);
                vm.z = fetch_lut(msb, mode, base + 2); vm.w = fetch_lut(msb, mode, base + 3);
                vl.x = fetch_lut(lsb, mode, base + 0); vl.y = fetch_lut(lsb, mode, base + 1);
                vl.z = fetch_lut(lsb, mode, base + 2); vl.w = fetch_lut(lsb, mode, base + 3);
                g_stage[j * 10 + q]     = vm;
                g_stage[j * 10 + 5 + q] = vl;
            }
        }
    }

    // ---------------- joint histogram ----------------
    const float4* __restrict__ a0 = (const float4*)(x_in);
    const float4* __restrict__ a1 = (const float4*)(x_in + PLANE);
    const float4* __restrict__ a2 = (const float4*)(x_in + 2 * PLANE);
    const float4* __restrict__ b0 = (const float4*)(x_s);
    const float4* __restrict__ b1 = (const float4*)(x_s + PLANE);
    const float4* __restrict__ b2 = (const float4*)(x_s + 2 * PLANE);

    const int NP     = PLANE / 8;                // pairs of float4 positions
    const int stride = K1_BLOCKS * K1_THREADS;

    for (int p = blockIdx.x * K1_THREADS + tid; p < NP; p += stride) {
        const int i0 = 2 * p, i1 = 2 * p + 1;
        // 12 independent streaming loads in flight per thread.
        float4 va0 = __ldcs(&a0[i0]); float4 va1 = __ldcs(&a0[i1]);
        float4 vb0 = __ldcs(&a1[i0]); float4 vb1 = __ldcs(&a1[i1]);
        float4 vc0 = __ldcs(&a2[i0]); float4 vc1 = __ldcs(&a2[i1]);
        float4 wa0 = __ldcs(&b0[i0]); float4 wa1 = __ldcs(&b0[i1]);
        float4 wb0 = __ldcs(&b1[i0]); float4 wb1 = __ldcs(&b1[i1]);
        float4 wc0 = __ldcs(&b2[i0]); float4 wc1 = __ldcs(&b2[i1]);

        // key = 289*a + 17*b + c  (exact in fp32: max 4912 < 2^24)
        atomicAdd(&hm[(int)fmaf(289.f, va0.x, fmaf(17.f, vb0.x, vc0.x))], 1u);
        atomicAdd(&hm[(int)fmaf(289.f, va0.y, fmaf(17.f, vb0.y, vc0.y))], 1u);
        atomicAdd(&hm[(int)fmaf(289.f, va0.z, fmaf(17.f, vb0.z, vc0.z))], 1u);
        atomicAdd(&hm[(int)fmaf(289.f, va0.w, fmaf(17.f, vb0.w, vc0.w))], 1u);
        atomicAdd(&hm[(int)fmaf(289.f, va1.x, fmaf(17.f, vb1.x, vc1.x))], 1u);
        atomicAdd(&hm[(int)fmaf(289.f, va1.y, fmaf(17.f, vb1.y, vc1.y))], 1u);
        atomicAdd(&hm[(int)fmaf(289.f, va1.z, fmaf(17.f, vb1.z, vc1.z))], 1u);
        atomicAdd(&hm[(int)fmaf(289.f, va1.w, fmaf(17.f, vb1.w, vc1.w))], 1u);

        atomicAdd(&hl[(int)fmaf(289.f, wa0.x, fmaf(17.f, wb0.x, wc0.x))], 1u);
        atomicAdd(&hl[(int)fmaf(289.f, wa0.y, fmaf(17.f, wb0.y, wc0.y))], 1u);
        atomicAdd(&hl[(int)fmaf(289.f, wa0.z, fmaf(17.f, wb0.z, wc0.z))], 1u);
        atomicAdd(&hl[(int)fmaf(289.f, wa0.w, fmaf(17.f, wb0.w, wc0.w))], 1u);
        atomicAdd(&hl[(int)fmaf(289.f, wa1.x, fmaf(17.f, wb1.x, wc1.x))], 1u);
        atomicAdd(&hl[(int)fmaf(289.f, wa1.y, fmaf(17.f, wb1.y, wc1.y))], 1u);
        atomicAdd(&hl[(int)fmaf(289.f, wa1.z, fmaf(17.f, wb1.z, wc1.z))], 1u);
        atomicAdd(&hl[(int)fmaf(289.f, wa1.w, fmaf(17.f, wb1.w, wc1.w))], 1u);
    }
    __syncthreads();

    // Flush into single global histogram (REDG, spread addresses).
    for (int k = tid; k < NBINS; k += K1_THREADS) {
        unsigned int vm = hm[k], vl = hl[k];
        if (vm) atomicAdd(&g_hist[k], vm);
        if (vl) atomicAdd(&g_hist[NBINS + k], vl);
    }
}

// ---------------------------------------------------------------------------
// Kernel 2 (reduce + final): branch-free, fully coalesced. Thread j issues
// 2 count loads + 10 CONTIGUOUS int4 loads from the normalized staging array
// (L2-warm — written by kernel 1), all independent -> single latency round.
// REDUX warp sums, one global atomic per feature, ticket finish.
// Consumed state (g_hist, g_accum, g_ticket) re-zeroed for the next launch.
// All sums fit int32 (|S| <= 2 * 4.2M * 32 ~= 2.7e8 < 2^31).
// ---------------------------------------------------------------------------
__global__ void __launch_bounds__(K2_THREADS)
reduce_final_kernel(float* __restrict__ out)
{
    __shared__ int s_part[K2_WARPS][NFEAT];
    __shared__ int s_last;
    const int tid  = threadIdx.x;
    const int wid  = tid >> 5;
    const int lane = tid & 31;

    const int j = blockIdx.x * K2_THREADS + tid;
    const bool active = (j < NBINS);

    int cm = 0, cl = 0;
    int4 c[10];
    if (active) {
        cm = (int)g_hist[j];
        cl = (int)g_hist[NBINS + j];
        const int4* row = &g_stage[j * 10];
        #pragma unroll
        for (int q = 0; q < 10; q++) c[q] = row[q];   // 160B contiguous per thread
        g_hist[j] = 0u;                               // zero-on-consume
        g_hist[NBINS + j] = 0u;
    } else {
        #pragma unroll
        for (int q = 0; q < 10; q++) c[q] = make_int4(0, 0, 0, 0);
    }

    int vals[NFEAT];
    #pragma unroll
    for (int q = 0; q < 5; q++) {
        vals[4*q+0] = cm * c[q].x + cl * c[5+q].x;
        vals[4*q+1] = cm * c[q].y + cl * c[5+q].y;
        vals[4*q+2] = cm * c[q].z + cl * c[5+q].z;
        vals[4*q+3] = cm * c[q].w + cl * c[5+q].w;
    }

    // Warp-level sums via REDUX; lane f keeps feature f's warp sum.
    int mine = 0;
    #pragma unroll
    for (int f = 0; f < NFEAT; f++) {
        int s = __reduce_add_sync(0xffffffffu, vals[f]);
        if (lane == f) mine = s;
    }
    if (lane < NFEAT) s_part[wid][lane] = mine;
    __syncthreads();

    if (tid < NFEAT) {
        int r = 0;
        #pragma unroll
        for (int w = 0; w < K2_WARPS; w++) r += s_part[w][tid];
        atomicAdd(&g_accum[tid], r);
    }
    __threadfence();
    __syncthreads();

    if (tid == 0) {
        unsigned int t = atomicAdd(&g_ticket, 1u);
        s_last = (t == K2_BLOCKS - 1) ? 1 : 0;
    }
    __syncthreads();

    if (s_last && tid < NFEAT) {
        // Coherent read (L2 atomic), then reset for next launch.
        int S = atomicAdd(&g_accum[tid], 0);
        g_accum[tid] = 0;
        if (tid == 0) g_ticket = 0u;
        // out = clip(round(mean*4)/4, -32, 31.75)
        //     = clamp(rint(S / 2^20), -128, 127) * 0.25   (exact in double)
        double q = rint((double)S / 1048576.0);
        q = fmin(fmax(q, -128.0), 127.0);
        out[tid] = (float)(q * 0.25);
    }
}

// ---------------------------------------------------------------------------
extern "C" void kernel_launch(void* const* d_in, const int* in_sizes, int n_in,
                              void* d_out, int out_size)
{
    const float* x_in = (const float*)d_in[0];
    const float* x_s  = (const float*)d_in[1];
    const void*  msb  = d_in[2];
    const void*  lsb  = d_in[3];
    float*       out  = (float*)d_out;

    hist_kernel<<<K1_BLOCKS, K1_THREADS>>>(x_in, x_s, msb, lsb);
    reduce_final_kernel<<<K2_BLOCKS, K2_THREADS>>>(out);
}

// round 10
// speedup vs baseline: 1.0890x; 1.0890x over previous
#include <cuda_runtime.h>
#include <cuda_bf16.h>
#include <cstdint>
#include <math.h>

// Problem constants
#define PLANE   (2048*2048)       // 4,194,304 pixels per channel plane
#define NBINS   4913              // 17^3 distinct compact keys (289a+17b+c)
#define NFEAT   20

#define K1_BLOCKS  148
#define K1_THREADS 1024
#define K2_THREADS 256
#define K2_WARPS   (K2_THREADS / 32)
#define K2_BLOCKS  ((NBINS + K2_THREADS - 1) / K2_THREADS)   // 20

#define MODE_INT8   0
#define MODE_INT32  1
#define MODE_FP32   2
#define MODE_BF16   3

// Staging work partition: 4913 bins x 5 int4 chunks = 24565 chunk-pairs
#define STAGE_TOTAL (NBINS * 5)
#define STAGE_PER_B ((STAGE_TOTAL + K1_BLOCKS - 1) / K1_BLOCKS)   // 166

// ---------------------------------------------------------------------------
// Global scratch. CUDA zeroes __device__ globals at module load. Invariant
// across launches / graph replays: g_hist, g_accum, g_ticket are ZERO on
// entry — kernel 2 re-zeroes everything it consumes. g_stage is fully
// overwritten every launch from constant inputs -> deterministic.
// ---------------------------------------------------------------------------
__device__ unsigned int g_hist[2 * NBINS];   // [msb bins | lsb bins]
__device__ int          g_accum[NFEAT];
__device__ unsigned int g_ticket;
// Compact, int32-normalized LUT rows: bin j -> 10 int4 = {msb[20] | lsb[20]}
__device__ int4         g_stage[NBINS * 10]; // 786 KB

// Scalar fetch for non-int32 upcast modes (fallback path only).
__device__ __forceinline__ int fetch_lut(const void* __restrict__ tab, int mode, long long e)
{
    switch (mode) {
        case MODE_FP32:  return (int)((const float*)tab)[e];
        case MODE_BF16:  return (int)__bfloat162float(((const __nv_bfloat16*)tab)[e]);
        default:         return (int)((const signed char*)tab)[e];
    }
}

// ---------------------------------------------------------------------------
// Kernel 1: joint histogram + LUT staging (warp 0 only).
// ATOMS-bound (~15us). Staging = ~166 int4-pairs per block, done by warp 0
// alone (mode sniffed in-warp, no cross-warp dependency) while the other 31
// warps run the hist mainloop -> staging latency fully hidden.
// ---------------------------------------------------------------------------
__global__ void __launch_bounds__(K1_THREADS, 1)
hist_kernel(const float* __restrict__ x_in, const float* __restrict__ x_s,
            const void* __restrict__ msb, const void* __restrict__ lsb)
{
    __shared__ unsigned int hm[NBINS];
    __shared__ unsigned int hl[NBINS];

    const int tid = threadIdx.x;
    for (int k = tid; k < NBINS; k += K1_THREADS) { hm[k] = 0u; hl[k] = 0u; }
    __syncthreads();

    // --- warp 0: dtype sniff + this block's slice of LUT staging ---
    if (tid < 32) {
        const int lane = tid;
        const int* w = (const int*)msb;
        int v[8];
        #pragma unroll
        for (int s = 0; s < 8; s++) v[s] = w[lane + 32 * s];

        bool small = true, flt = true, bfl = true;
        #pragma unroll
        for (int s = 0; s < 8; s++) {
            int x = v[s];
            if (x < -32 || x > 31) small = false;
            float f = __int_as_float(x);
            if (!(isfinite(f) && f == truncf(f) && fabsf(f) <= 32.f)) flt = false;
            unsigned u = (unsigned)x;
            float h0 = __bfloat162float(__ushort_as_bfloat16((unsigned short)(u & 0xFFFFu)));
            float h1 = __bfloat162float(__ushort_as_bfloat16((unsigned short)(u >> 16)));
            if (!(isfinite(h0) && h0 == truncf(h0) && fabsf(h0) <= 32.f &&
                  isfinite(h1) && h1 == truncf(h1) && fabsf(h1) <= 32.f)) bfl = false;
        }
        int mode;
        if      (__all_sync(0xffffffffu, small)) mode = MODE_INT32;
        else if (__all_sync(0xffffffffu, flt))   mode = MODE_FP32;
        else if (__all_sync(0xffffffffu, bfl))   mode = MODE_BF16;
        else                                     mode = MODE_INT8;

        // Stage chunk-pairs [base, end) : chunk t -> bin j=t/5, quarter q=t%5
        const int base = blockIdx.x * STAGE_PER_B;
        int end = base + STAGE_PER_B; if (end > STAGE_TOTAL) end = STAGE_TOTAL;
        if (mode == MODE_INT32) {
            const int4* m4 = (const int4*)msb;
            const int4* l4 = (const int4*)lsb;
            for (int t = base + lane; t < end; t += 32) {
                const int j = t / 5, q = t - 5 * j;
                g_stage[j * 10 + q]     = m4[80L * j + q];
                g_stage[j * 10 + 5 + q] = l4[80L * j + q];
            }
        } else {
            for (int t = base + lane; t < end; t += 32) {
                const int j = t / 5, q = t - 5 * j;
                const long long e = 320LL * j + 4LL * q;
                int4 vm, vl;
                vm.x = fetch_lut(msb, mode, e + 0); vm.y = fetch_lut(msb, mode, e + 1);
                vm.z = fetch_lut(msb, mode, e + 2); vm.w = fetch_lut(msb, mode, e + 3);
                vl.x = fetch_lut(lsb, mode, e + 0); vl.y = fetch_lut(lsb, mode, e + 1);
                vl.z = fetch_lut(lsb, mode, e + 2); vl.w = fetch_lut(lsb, mode, e + 3);
                g_stage[j * 10 + q]     = vm;
                g_stage[j * 10 + 5 + q] = vl;
            }
        }
    }

    // ---------------- joint histogram ----------------
    const float4* __restrict__ a0 = (const float4*)(x_in);
    const float4* __restrict__ a1 = (const float4*)(x_in + PLANE);
    const float4* __restrict__ a2 = (const float4*)(x_in + 2 * PLANE);
    const float4* __restrict__ b0 = (const float4*)(x_s);
    const float4* __restrict__ b1 = (const float4*)(x_s + PLANE);
    const float4* __restrict__ b2 = (const float4*)(x_s + 2 * PLANE);

    const int NP     = PLANE / 8;                // pairs of float4 positions
    const int stride = K1_BLOCKS * K1_THREADS;

    for (int p = blockIdx.x * K1_THREADS + tid; p < NP; p += stride) {
        const int i0 = 2 * p, i1 = 2 * p + 1;
        // 12 independent streaming loads in flight per thread.
        float4 va0 = __ldcs(&a0[i0]); float4 va1 = __ldcs(&a0[i1]);
        float4 vb0 = __ldcs(&a1[i0]); float4 vb1 = __ldcs(&a1[i1]);
        float4 vc0 = __ldcs(&a2[i0]); float4 vc1 = __ldcs(&a2[i1]);
        float4 wa0 = __ldcs(&b0[i0]); float4 wa1 = __ldcs(&b0[i1]);
        float4 wb0 = __ldcs(&b1[i0]); float4 wb1 = __ldcs(&b1[i1]);
        float4 wc0 = __ldcs(&b2[i0]); float4 wc1 = __ldcs(&b2[i1]);

        // key = 289*a + 17*b + c  (exact in fp32: max 4912 < 2^24)
        atomicAdd(&hm[(int)fmaf(289.f, va0.x, fmaf(17.f, vb0.x, vc0.x))], 1u);
        atomicAdd(&hm[(int)fmaf(289.f, va0.y, fmaf(17.f, vb0.y, vc0.y))], 1u);
        atomicAdd(&hm[(int)fmaf(289.f, va0.z, fmaf(17.f, vb0.z, vc0.z))], 1u);
        atomicAdd(&hm[(int)fmaf(289.f, va0.w, fmaf(17.f, vb0.w, vc0.w))], 1u);
        atomicAdd(&hm[(int)fmaf(289.f, va1.x, fmaf(17.f, vb1.x, vc1.x))], 1u);
        atomicAdd(&hm[(int)fmaf(289.f, va1.y, fmaf(17.f, vb1.y, vc1.y))], 1u);
        atomicAdd(&hm[(int)fmaf(289.f, va1.z, fmaf(17.f, vb1.z, vc1.z))], 1u);
        atomicAdd(&hm[(int)fmaf(289.f, va1.w, fmaf(17.f, vb1.w, vc1.w))], 1u);

        atomicAdd(&hl[(int)fmaf(289.f, wa0.x, fmaf(17.f, wb0.x, wc0.x))], 1u);
        atomicAdd(&hl[(int)fmaf(289.f, wa0.y, fmaf(17.f, wb0.y, wc0.y))], 1u);
        atomicAdd(&hl[(int)fmaf(289.f, wa0.z, fmaf(17.f, wb0.z, wc0.z))], 1u);
        atomicAdd(&hl[(int)fmaf(289.f, wa0.w, fmaf(17.f, wb0.w, wc0.w))], 1u);
        atomicAdd(&hl[(int)fmaf(289.f, wa1.x, fmaf(17.f, wb1.x, wc1.x))], 1u);
        atomicAdd(&hl[(int)fmaf(289.f, wa1.y, fmaf(17.f, wb1.y, wc1.y))], 1u);
        atomicAdd(&hl[(int)fmaf(289.f, wa1.z, fmaf(17.f, wb1.z, wc1.z))], 1u);
        atomicAdd(&hl[(int)fmaf(289.f, wa1.w, fmaf(17.f, wb1.w, wc1.w))], 1u);
    }
    __syncthreads();

    // Flush into single global histogram (REDG, spread addresses).
    for (int k = tid; k < NBINS; k += K1_THREADS) {
        unsigned int vm = hm[k], vl = hl[k];
        if (vm) atomicAdd(&g_hist[k], vm);
        if (vl) atomicAdd(&g_hist[NBINS + k], vl);
    }
}

// ---------------------------------------------------------------------------
// Kernel 2 (reduce + final): branch-free, fully coalesced (R9-measured 6.6us).
// Thread j: 2 count loads + 10 CONTIGUOUS int4 loads from the normalized
// staging array, all independent -> single latency round. REDUX warp sums,
// one global atomic per feature, ticket finish. Consumed state re-zeroed.
// All sums fit int32 (|S| <= 2 * 4.2M * 32 ~= 2.7e8 < 2^31).
// ---------------------------------------------------------------------------
__global__ void __launch_bounds__(K2_THREADS)
reduce_final_kernel(float* __restrict__ out)
{
    __shared__ int s_part[K2_WARPS][NFEAT];
    __shared__ int s_last;
    const int tid  = threadIdx.x;
    const int wid  = tid >> 5;
    const int lane = tid & 31;

    const int j = blockIdx.x * K2_THREADS + tid;
    const bool active = (j < NBINS);

    int cm = 0, cl = 0;
    int4 c[10];
    if (active) {
        cm = (int)g_hist[j];
        cl = (int)g_hist[NBINS + j];
        const int4* row = &g_stage[j * 10];
        #pragma unroll
        for (int q = 0; q < 10; q++) c[q] = row[q];   // 160B contiguous per thread
        g_hist[j] = 0u;                               // zero-on-consume
        g_hist[NBINS + j] = 0u;
    } else {
        #pragma unroll
        for (int q = 0; q < 10; q++) c[q] = make_int4(0, 0, 0, 0);
    }

    int vals[NFEAT];
    #pragma unroll
    for (int q = 0; q < 5; q++) {
        vals[4*q+0] = cm * c[q].x + cl * c[5+q].x;
        vals[4*q+1] = cm * c[q].y + cl * c[5+q].y;
        vals[4*q+2] = cm * c[q].z + cl * c[5+q].z;
        vals[4*q+3] = cm * c[q].w + cl * c[5+q].w;
    }

    // Warp-level sums via REDUX; lane f keeps feature f's warp sum.
    int mine = 0;
    #pragma unroll
    for (int f = 0; f < NFEAT; f++) {
        int s = __reduce_add_sync(0xffffffffu, vals[f]);
        if (lane == f) mine = s;
    }
    if (lane < NFEAT) s_part[wid][lane] = mine;
    __syncthreads();

    if (tid < NFEAT) {
        int r = 0;
        #pragma unroll
        for (int w = 0; w < K2_WARPS; w++) r += s_part[w][tid];
        atomicAdd(&g_accum[tid], r);
    }
    __threadfence();
    __syncthreads();

    if (tid == 0) {
        unsigned int t = atomicAdd(&g_ticket, 1u);
        s_last = (t == K2_BLOCKS - 1) ? 1 : 0;
    }
    __syncthreads();

    if (s_last && tid < NFEAT) {
        // Coherent read (L2 atomic), then reset for next launch.
        int S = atomicAdd(&g_accum[tid], 0);
        g_accum[tid] = 0;
        if (tid == 0) g_ticket = 0u;
        // out = clip(round(mean*4)/4, -32, 31.75)
        //     = clamp(rint(S / 2^20), -128, 127) * 0.25   (exact in double)
        double q = rint((double)S / 1048576.0);
        q = fmin(fmax(q, -128.0), 127.0);
        out[tid] = (float)(q * 0.25);
    }
}

// ---------------------------------------------------------------------------
extern "C" void kernel_launch(void* const* d_in, const int* in_sizes, int n_in,
                              void* d_out, int out_size)
{
    const float* x_in = (const float*)d_in[0];
    const float* x_s  = (const float*)d_in[1];
    const void*  msb  = d_in[2];
    const void*  lsb  = d_in[3];
    float*       out  = (float*)d_out;

    hist_kernel<<<K1_BLOCKS, K1_THREADS>>>(x_in, x_s, msb, lsb);
    reduce_final_kernel<<<K2_BLOCKS, K2_THREADS>>>(out);
}